// round 16
// baseline (speedup 1.0000x reference)
#include <cuda_runtime.h>
#include <cstdint>

// Problem constants (fixed shapes from reference)
#define HEADS   16
#define HDIM    128
#define EMB     2048
#define EMB3    6144
#define SEQ     2048
#define BATCH   2
#define MROWS   (BATCH*SEQ)        // 4096

// Scratch (allocation-free rule: __device__ globals).
// All inter-kernel tensors carry tf32 bit patterns in uint32.
__device__ uint32_t g_q[(size_t)BATCH*HEADS*SEQ*HDIM];
__device__ uint32_t g_k[(size_t)BATCH*HEADS*SEQ*HDIM];
__device__ uint32_t g_v[(size_t)BATCH*HEADS*SEQ*HDIM];
__device__ uint32_t g_att[(size_t)MROWS*EMB];
__device__ uint32_t g_xt[(size_t)MROWS*EMB];
__device__ uint32_t g_wqt[(size_t)EMB3*EMB];
__device__ uint32_t g_wpt[(size_t)EMB*EMB];

// ---------- helpers ----------
__device__ __forceinline__ uint32_t smem_u32(const void* p) {
    uint32_t a;
    asm("{ .reg .u64 t; cvta.to.shared.u64 t, %1; cvt.u32.u64 %0, t; }"
        : "=r"(a) : "l"(p));
    return a;
}
__device__ __forceinline__ uint32_t f2tf32(float f) {
    uint32_t r;
    asm("cvt.rna.tf32.f32 %0, %1;" : "=r"(r) : "f"(f));
    return r;
}
__device__ __forceinline__ void mma_tf32(float* c, const uint32_t* a,
                                         uint32_t b0, uint32_t b1) {
    asm volatile(
        "mma.sync.aligned.m16n8k8.row.col.f32.tf32.tf32.f32 "
        "{%0,%1,%2,%3}, {%4,%5,%6,%7}, {%8,%9}, {%0,%1,%2,%3};"
        : "+f"(c[0]), "+f"(c[1]), "+f"(c[2]), "+f"(c[3])
        : "r"(a[0]), "r"(a[1]), "r"(a[2]), "r"(a[3]), "r"(b0), "r"(b1));
}
#define CP_ASYNC16(dst, src) \
    asm volatile("cp.async.cg.shared.global [%0], [%1], 16;" \
                 :: "r"(dst), "l"(src))
#define CP_COMMIT()  asm volatile("cp.async.commit_group;" ::: "memory")
#define CP_WAIT0()   asm volatile("cp.async.wait_group 0;" ::: "memory")
#define CP_WAIT1()   asm volatile("cp.async.wait_group 1;" ::: "memory")

// ---------- fused prepass: fp32 -> tf32 bits for x, Wqkv, Wproj ----------
#define N1U4 ((MROWS*EMB)   / 4)    // x:     2,097,152 uint4
#define N2U4 ((EMB3*EMB)    / 4)    // Wqkv:  3,145,728 uint4
#define N3U4 ((EMB*EMB)     / 4)    // Wproj: 1,048,576 uint4
#define NTOTU4 (N1U4 + N2U4 + N3U4)

__global__ void __launch_bounds__(256) cvt_all_kernel(
    const float* __restrict__ x, const float* __restrict__ wq,
    const float* __restrict__ wp)
{
    int i = blockIdx.x * blockDim.x + threadIdx.x;
    int stride = gridDim.x * blockDim.x;
    for (; i < NTOTU4; i += stride) {
        const float4* src;
        uint4* dst;
        if (i < N1U4)            { src = (const float4*)x  + i;
                                   dst = (uint4*)g_xt + i; }
        else if (i < N1U4+N2U4)  { src = (const float4*)wq + (i - N1U4);
                                   dst = (uint4*)g_wqt + (i - N1U4); }
        else                     { src = (const float4*)wp + (i - N1U4 - N2U4);
                                   dst = (uint4*)g_wpt + (i - N1U4 - N2U4); }
        float4 v = *src;
        *dst = make_uint4(f2tf32(v.x), f2tf32(v.y), f2tf32(v.z), f2tf32(v.w));
    }
}

// =====================================================================
// TF32 tensor-core GEMM v6 (R9/R12/R15 WIN, verbatim): 128x128x32 block,
// 128 threads, 4 warps @ 64x64, 3-stage cp.async, 2 blocks/SM.
// MODE 0: A=g_xt, B=g_wqt; epilogue scatters tf32 bits into g_q/g_k/g_v
// MODE 1: A=g_att, B=g_wpt; epilogue writes fp32 C
// =====================================================================
#define GBM 128
#define GBN 128
#define GBK 32
#define NSTAGE 3
#define TILE_W   (GBM * GBK)
#define STAGE_W  (2 * TILE_W)
#define GEMM_SMEM_BYTES (NSTAGE * STAGE_W * 4)   // 98304

template<int MODE>
__global__ void __launch_bounds__(128, 2) sgemm_tf32_v6(
    float* __restrict__ C, int M, int N, int K)
{
    extern __shared__ uint32_t sm[];
    const uint32_t sbase = smem_u32(sm);

    const uint32_t* Ap = (MODE == 1) ? g_att : g_xt;
    const uint32_t* Bw = (MODE == 1) ? g_wpt : g_wqt;

    const int tid  = threadIdx.x;
    const int warp = tid >> 5;
    const int lane = tid & 31;
    const int g    = lane >> 2;
    const int q    = lane & 3;

    const int bm = blockIdx.y * GBM;
    const int bn = blockIdx.x * GBN;
    const int wm = (warp >> 1) * 64;
    const int wn = (warp & 1) * 64;

    const int srow = tid >> 3;
    const int scc  = tid & 7;
    uint32_t soff[8];
#pragma unroll
    for (int p = 0; p < 8; p++) {
        int r = p * 16 + srow;
        soff[p] = (uint32_t)r * GBK + (uint32_t)((scc ^ (r & 7)) * 4);
    }

    float acc[4][8][4];
#pragma unroll
    for (int i = 0; i < 4; i++)
#pragma unroll
        for (int j = 0; j < 8; j++)
#pragma unroll
            for (int e = 0; e < 4; e++) acc[i][j][e] = 0.f;

    const int NIT = K / GBK;

#pragma unroll
    for (int s = 0; s < 2; s++) {
        const uint32_t dA = sbase + (uint32_t)(s * STAGE_W) * 4;
        const uint32_t dB = dA + TILE_W * 4;
        const int k0 = s * GBK;
#pragma unroll
        for (int p = 0; p < 8; p++) {
            const uint32_t* as = Ap + (size_t)(bm + p * 16 + srow) * K + k0 + scc * 4;
            const uint32_t* bs = Bw + (size_t)(bn + p * 16 + srow) * K + k0 + scc * 4;
            CP_ASYNC16(dA + soff[p] * 4, as);
            CP_ASYNC16(dB + soff[p] * 4, bs);
        }
        CP_COMMIT();
    }

    for (int it = 0; it < NIT; it++) {
        CP_WAIT1();
        __syncthreads();

        if (it + 2 < NIT) {
            const int b2 = (it + 2) % NSTAGE;
            const uint32_t dA = sbase + (uint32_t)(b2 * STAGE_W) * 4;
            const uint32_t dB = dA + TILE_W * 4;
            const int k0 = (it + 2) * GBK;
#pragma unroll
            for (int p = 0; p < 8; p++) {
                const uint32_t* as = Ap + (size_t)(bm + p * 16 + srow) * K + k0 + scc * 4;
                const uint32_t* bs = Bw + (size_t)(bn + p * 16 + srow) * K + k0 + scc * 4;
                CP_ASYNC16(dA + soff[p] * 4, as);
                CP_ASYNC16(dB + soff[p] * 4, bs);
            }
        }
        CP_COMMIT();

        const uint32_t* As = sm + (it % NSTAGE) * STAGE_W;
        const uint32_t* Bs = As + TILE_W;
#pragma unroll
        for (int ks = 0; ks < 4; ks++) {
            const int qa0 = ((2 * ks)     ^ g) * 4 + q;
            const int qa1 = ((2 * ks + 1) ^ g) * 4 + q;
            uint32_t a[4][4];
#pragma unroll
            for (int i = 0; i < 4; i++) {
                const int m0 = wm + i * 16 + g;
                a[i][0] = As[m0 * GBK + qa0];
                a[i][1] = As[(m0 + 8) * GBK + qa0];
                a[i][2] = As[m0 * GBK + qa1];
                a[i][3] = As[(m0 + 8) * GBK + qa1];
            }
#pragma unroll
            for (int j = 0; j < 8; j++) {
                const int n0 = wn + j * 8 + g;
                const uint32_t b0 = Bs[n0 * GBK + qa0];
                const uint32_t b1 = Bs[n0 * GBK + qa1];
#pragma unroll
                for (int i = 0; i < 4; i++)
                    mma_tf32(acc[i][j], a[i], b0, b1);
            }
        }
    }

#pragma unroll
    for (int i = 0; i < 4; i++) {
#pragma unroll
        for (int j = 0; j < 8; j++) {
            int r0 = bm + wm + i * 16 + g;
            int n0 = bn + wn + j * 8 + 2 * q;
            if (MODE == 0) {
                int which = n0 >> 11;
                int hh    = (n0 >> 7) & (HEADS - 1);
                int d     = n0 & (HDIM - 1);
                int b     = r0 >> 11;
                uint32_t* base = (which == 0 ? g_q : which == 1 ? g_k : g_v)
                                 + ((size_t)(b * HEADS + hh)) * SEQ * HDIM;
                int s0 = r0 & (SEQ - 1);
                *(uint2*)&base[(size_t)s0 * HDIM + d] =
                    make_uint2(f2tf32(acc[i][j][0]), f2tf32(acc[i][j][1]));
                *(uint2*)&base[(size_t)(s0 + 8) * HDIM + d] =
                    make_uint2(f2tf32(acc[i][j][2]), f2tf32(acc[i][j][3]));
            } else {
                *(float2*)(C + (size_t)r0 * N + n0) =
                    make_float2(acc[i][j][0], acc[i][j][1]);
                *(float2*)(C + (size_t)(r0 + 8) * N + n0) =
                    make_float2(acc[i][j][2], acc[i][j][3]);
            }
        }
    }
}

// =====================================================================
// TF32 tensor-core flash attention (R15 WIN structure, verbatim 2-barrier
// schedule with cp.async staging; ONLY change: Q fragments pre-scaled by
// 1/sqrt(D) at build time, per-tile score-scale loop removed).
// Block = (64 q-rows, head, batch), 128 threads = 4 warps x 16-row tiles,
// longest blocks first.
// =====================================================================
#define AT_BR 64
#define AT_BC 64
#define KST   132
#define PST   68
#define ATTN_SMEM_WORDS (2 * AT_BC * KST + AT_BR * PST)
#define ATTN_SMEM_BYTES (ATTN_SMEM_WORDS * 4)

__global__ void __launch_bounds__(128) attn_tf32_kernel()
{
    extern __shared__ uint32_t smw[];
    const uint32_t sbase = smem_u32(smw);
    uint32_t* Ks = smw;
    uint32_t* Vs = Ks + AT_BC * KST;
    uint32_t* Ps = Vs + AT_BC * KST;
    const uint32_t vbase = sbase + (uint32_t)(AT_BC * KST) * 4;

    const int t    = threadIdx.x;
    const int warp = t >> 5;
    const int lane = t & 31;
    const int g    = lane >> 2;
    const int q    = lane & 3;
    const int wrow = warp * 16;

    const int qt = (gridDim.x - 1) - blockIdx.x;   // longest blocks first
    const int h  = blockIdx.y, b = blockIdx.z;
    const int q0 = qt * AT_BR;
    const size_t headBase = ((size_t)(b * HEADS + h)) * SEQ * HDIM;
    const float scale = 0.08838834764831845f;   // 1/sqrt(128)

    // stage Q tile via cp.async (layout [row][KST])
    {
        const uint32_t* Qg = g_q + headBase + (size_t)q0 * HDIM;
#pragma unroll
        for (int i = 0; i < 16; i++) {
            int idx = t + i * 128;
            int row = idx >> 5, c = idx & 31;
            CP_ASYNC16(sbase + (uint32_t)(row * KST + c * 4) * 4,
                       Qg + (size_t)row * HDIM + c * 4);
        }
        CP_COMMIT();
        CP_WAIT0();
    }
    __syncthreads();

    // Q fragments pre-scaled by 1/sqrt(D) (one-time; removes the per-tile
    // score-scale FMA loop from the softmax critical section)
    uint32_t qf[16][4];
#pragma unroll
    for (int ks = 0; ks < 16; ks++) {
        qf[ks][0] = f2tf32(__uint_as_float(Ks[(wrow + g)     * KST + ks * 8 + q]) * scale);
        qf[ks][1] = f2tf32(__uint_as_float(Ks[(wrow + g + 8) * KST + ks * 8 + q]) * scale);
        qf[ks][2] = f2tf32(__uint_as_float(Ks[(wrow + g)     * KST + ks * 8 + q + 4]) * scale);
        qf[ks][3] = f2tf32(__uint_as_float(Ks[(wrow + g + 8) * KST + ks * 8 + q + 4]) * scale);
    }

    float accO[16][4];
#pragma unroll
    for (int n = 0; n < 16; n++)
#pragma unroll
        for (int e = 0; e < 4; e++) accO[n][e] = 0.f;

    float m0r = -1e30f, m1r = -1e30f;
    float l0r = 0.f, l1r = 0.f;

    for (int kt = 0; kt <= qt; kt++) {
        __syncthreads();   // previous tile's K/V/P readers done
        {
            const uint32_t* Kg = g_k + headBase + (size_t)(kt * AT_BC) * HDIM;
            const uint32_t* Vg = g_v + headBase + (size_t)(kt * AT_BC) * HDIM;
#pragma unroll
            for (int i = 0; i < 16; i++) {
                int idx = t + i * 128;
                int row = idx >> 5, c = idx & 31;
                const uint32_t off = (uint32_t)(row * KST + c * 4) * 4;
                CP_ASYNC16(sbase + off, Kg + (size_t)row * HDIM + c * 4);
                CP_ASYNC16(vbase + off, Vg + (size_t)row * HDIM + c * 4);
            }
            CP_COMMIT();
            CP_WAIT0();
        }
        __syncthreads();

        float sc[8][4];
#pragma unroll
        for (int n = 0; n < 8; n++)
#pragma unroll
            for (int e = 0; e < 4; e++) sc[n][e] = 0.f;

#pragma unroll
        for (int ks = 0; ks < 16; ks++) {
#pragma unroll
            for (int n = 0; n < 8; n++) {
                uint32_t b0 = Ks[(n * 8 + g) * KST + ks * 8 + q];
                uint32_t b1 = Ks[(n * 8 + g) * KST + ks * 8 + q + 4];
                mma_tf32(sc[n], qf[ks], b0, b1);
            }
        }

        if (kt == qt) {
            int r0 = wrow + g, r1 = wrow + g + 8;
#pragma unroll
            for (int n = 0; n < 8; n++) {
                int c0 = n * 8 + 2 * q, c1 = c0 + 1;
                if (c0 > r0) sc[n][0] = -1e30f;
                if (c1 > r0) sc[n][1] = -1e30f;
                if (c0 > r1) sc[n][2] = -1e30f;
                if (c1 > r1) sc[n][3] = -1e30f;
            }
        }

        float pm0 = -1e30f, pm1 = -1e30f;
#pragma unroll
        for (int n = 0; n < 8; n++) {
            pm0 = fmaxf(pm0, fmaxf(sc[n][0], sc[n][1]));
            pm1 = fmaxf(pm1, fmaxf(sc[n][2], sc[n][3]));
        }
        pm0 = fmaxf(pm0, __shfl_xor_sync(0xffffffffu, pm0, 1));
        pm0 = fmaxf(pm0, __shfl_xor_sync(0xffffffffu, pm0, 2));
        pm1 = fmaxf(pm1, __shfl_xor_sync(0xffffffffu, pm1, 1));
        pm1 = fmaxf(pm1, __shfl_xor_sync(0xffffffffu, pm1, 2));

        float mn0 = fmaxf(m0r, pm0);
        float mn1 = fmaxf(m1r, pm1);
        float al0 = __expf(m0r - mn0);
        float al1 = __expf(m1r - mn1);
        m0r = mn0; m1r = mn1;

        float ps0 = 0.f, ps1 = 0.f;
#pragma unroll
        for (int n = 0; n < 8; n++) {
            float p00 = __expf(sc[n][0] - mn0);
            float p01 = __expf(sc[n][1] - mn0);
            float p10 = __expf(sc[n][2] - mn1);
            float p11 = __expf(sc[n][3] - mn1);
            ps0 += p00 + p01;
            ps1 += p10 + p11;
            uint32_t* pr0 = &Ps[(wrow + g) * PST + n * 8 + 2 * q];
            uint32_t* pr1 = &Ps[(wrow + g + 8) * PST + n * 8 + 2 * q];
            pr0[0] = f2tf32(p00); pr0[1] = f2tf32(p01);
            pr1[0] = f2tf32(p10); pr1[1] = f2tf32(p11);
        }
        ps0 += __shfl_xor_sync(0xffffffffu, ps0, 1);
        ps0 += __shfl_xor_sync(0xffffffffu, ps0, 2);
        ps1 += __shfl_xor_sync(0xffffffffu, ps1, 1);
        ps1 += __shfl_xor_sync(0xffffffffu, ps1, 2);
        l0r = l0r * al0 + ps0;
        l1r = l1r * al1 + ps1;

#pragma unroll
        for (int n = 0; n < 16; n++) {
            accO[n][0] *= al0; accO[n][1] *= al0;
            accO[n][2] *= al1; accO[n][3] *= al1;
        }

        __syncwarp();

#pragma unroll
        for (int ks = 0; ks < 8; ks++) {
            uint32_t pa[4];
            pa[0] = Ps[(wrow + g)     * PST + ks * 8 + q];
            pa[1] = Ps[(wrow + g + 8) * PST + ks * 8 + q];
            pa[2] = Ps[(wrow + g)     * PST + ks * 8 + q + 4];
            pa[3] = Ps[(wrow + g + 8) * PST + ks * 8 + q + 4];
#pragma unroll
            for (int n = 0; n < 16; n++) {
                uint32_t b0 = Vs[(ks * 8 + q)     * KST + n * 8 + g];
                uint32_t b1 = Vs[(ks * 8 + q + 4) * KST + n * 8 + g];
                mma_tf32(accO[n], pa, b0, b1);
            }
        }
        __syncwarp();
    }

    // epilogue: normalize, write tf32 bits to g_att
    float inv0 = 1.0f / l0r;
    float inv1 = 1.0f / l1r;
    size_t row0 = (size_t)(b * SEQ + q0 + wrow + g);
    size_t row1 = row0 + 8;
#pragma unroll
    for (int n = 0; n < 16; n++) {
        int d = n * 8 + 2 * q;
        *(uint2*)&g_att[row0 * EMB + h * HDIM + d] =
            make_uint2(f2tf32(accO[n][0] * inv0), f2tf32(accO[n][1] * inv0));
        *(uint2*)&g_att[row1 * EMB + h * HDIM + d] =
            make_uint2(f2tf32(accO[n][2] * inv1), f2tf32(accO[n][3] * inv1));
    }
}

// =====================================================================
// launch
// =====================================================================
extern "C" void kernel_launch(void* const* d_in, const int* in_sizes, int n_in,
                              void* d_out, int out_size)
{
    (void)in_sizes; (void)n_in; (void)out_size;
    const float* x     = (const float*)d_in[0];   // [B,S,E]
    const float* Wqkv  = (const float*)d_in[1];   // [3E,E]
    const float* Wproj = (const float*)d_in[2];   // [E,E]
    float* out = (float*)d_out;                   // [B,S,E]

    cudaFuncSetAttribute(sgemm_tf32_v6<0>,
                         cudaFuncAttributeMaxDynamicSharedMemorySize,
                         GEMM_SMEM_BYTES);
    cudaFuncSetAttribute(sgemm_tf32_v6<1>,
                         cudaFuncAttributeMaxDynamicSharedMemorySize,
                         GEMM_SMEM_BYTES);
    cudaFuncSetAttribute(attn_tf32_kernel,
                         cudaFuncAttributeMaxDynamicSharedMemorySize,
                         ATTN_SMEM_BYTES);

    // 0) fused prepass: fp32 -> tf32 bit buffers (one launch)
    cvt_all_kernel<<<2048, 256>>>(x, Wqkv, Wproj);

    // 1) qkv = x @ Wqkv^T -> g_q/g_k/g_v (tf32 bits, [B,H,S,D])
    dim3 g1(EMB3 / GBN, MROWS / GBM);
    sgemm_tf32_v6<0><<<g1, 128, GEMM_SMEM_BYTES>>>(nullptr, MROWS, EMB3, EMB);

    // 2) causal flash attention -> g_att (tf32 bits, [B,S,E])
    dim3 g2(SEQ / AT_BR, HEADS, BATCH);
    attn_tf32_kernel<<<g2, 128, ATTN_SMEM_BYTES>>>();

    // 3) out = g_att @ Wproj^T (fp32 out)
    dim3 g3(EMB / GBN, MROWS / GBM);
    sgemm_tf32_v6<1><<<g3, 128, GEMM_SMEM_BYTES>>>(out, MROWS, EMB, EMB);
}

// round 17
// speedup vs baseline: 1.0034x; 1.0034x over previous
#include <cuda_runtime.h>
#include <cstdint>

// Problem constants (fixed shapes from reference)
#define HEADS   16
#define HDIM    128
#define EMB     2048
#define EMB3    6144
#define SEQ     2048
#define BATCH   2
#define MROWS   (BATCH*SEQ)        // 4096

// Scratch (allocation-free rule: __device__ globals).
// All inter-kernel tensors carry tf32 bit patterns in uint32.
__device__ uint32_t g_q[(size_t)BATCH*HEADS*SEQ*HDIM];
__device__ uint32_t g_k[(size_t)BATCH*HEADS*SEQ*HDIM];
__device__ uint32_t g_v[(size_t)BATCH*HEADS*SEQ*HDIM];
__device__ uint32_t g_att[(size_t)MROWS*EMB];
__device__ uint32_t g_xt[(size_t)MROWS*EMB];
__device__ uint32_t g_wqt[(size_t)EMB3*EMB];
__device__ uint32_t g_wpt[(size_t)EMB*EMB];

// ---------- helpers ----------
__device__ __forceinline__ uint32_t smem_u32(const void* p) {
    uint32_t a;
    asm("{ .reg .u64 t; cvta.to.shared.u64 t, %1; cvt.u32.u64 %0, t; }"
        : "=r"(a) : "l"(p));
    return a;
}
__device__ __forceinline__ uint32_t f2tf32(float f) {
    uint32_t r;
    asm("cvt.rna.tf32.f32 %0, %1;" : "=r"(r) : "f"(f));
    return r;
}
__device__ __forceinline__ void mma_tf32(float* c, const uint32_t* a,
                                         uint32_t b0, uint32_t b1) {
    asm volatile(
        "mma.sync.aligned.m16n8k8.row.col.f32.tf32.tf32.f32 "
        "{%0,%1,%2,%3}, {%4,%5,%6,%7}, {%8,%9}, {%0,%1,%2,%3};"
        : "+f"(c[0]), "+f"(c[1]), "+f"(c[2]), "+f"(c[3])
        : "r"(a[0]), "r"(a[1]), "r"(a[2]), "r"(a[3]), "r"(b0), "r"(b1));
}
#define CP_ASYNC16(dst, src) \
    asm volatile("cp.async.cg.shared.global [%0], [%1], 16;" \
                 :: "r"(dst), "l"(src))
#define CP_COMMIT()  asm volatile("cp.async.commit_group;" ::: "memory")
#define CP_WAIT0()   asm volatile("cp.async.wait_group 0;" ::: "memory")
#define CP_WAIT1()   asm volatile("cp.async.wait_group 1;" ::: "memory")

// ---------- fused prepass: fp32 -> tf32 bits for x, Wqkv, Wproj ----------
#define N1U4 ((MROWS*EMB)   / 4)
#define N2U4 ((EMB3*EMB)    / 4)
#define N3U4 ((EMB*EMB)     / 4)
#define NTOTU4 (N1U4 + N2U4 + N3U4)

__global__ void __launch_bounds__(256) cvt_all_kernel(
    const float* __restrict__ x, const float* __restrict__ wq,
    const float* __restrict__ wp)
{
    int i = blockIdx.x * blockDim.x + threadIdx.x;
    int stride = gridDim.x * blockDim.x;
    for (; i < NTOTU4; i += stride) {
        const float4* src;
        uint4* dst;
        if (i < N1U4)            { src = (const float4*)x  + i;
                                   dst = (uint4*)g_xt + i; }
        else if (i < N1U4+N2U4)  { src = (const float4*)wq + (i - N1U4);
                                   dst = (uint4*)g_wqt + (i - N1U4); }
        else                     { src = (const float4*)wp + (i - N1U4 - N2U4);
                                   dst = (uint4*)g_wpt + (i - N1U4 - N2U4); }
        float4 v = *src;
        *dst = make_uint4(f2tf32(v.x), f2tf32(v.y), f2tf32(v.z), f2tf32(v.w));
    }
}

// =====================================================================
// TF32 tensor-core GEMM v6 (R9/R12/R15 WIN, verbatim): 128x128x32 block,
// 128 threads, 4 warps @ 64x64, 3-stage cp.async, 2 blocks/SM.
// MODE 0: A=g_xt, B=g_wqt; epilogue scatters tf32 bits into g_q/g_k/g_v
// MODE 1: A=g_att, B=g_wpt; epilogue writes fp32 C
// =====================================================================
#define GBM 128
#define GBN 128
#define GBK 32
#define NSTAGE 3
#define TILE_W   (GBM * GBK)
#define STAGE_W  (2 * TILE_W)
#define GEMM_SMEM_BYTES (NSTAGE * STAGE_W * 4)   // 98304

template<int MODE>
__global__ void __launch_bounds__(128, 2) sgemm_tf32_v6(
    float* __restrict__ C, int M, int N, int K)
{
    extern __shared__ uint32_t sm[];
    const uint32_t sbase = smem_u32(sm);

    const uint32_t* Ap = (MODE == 1) ? g_att : g_xt;
    const uint32_t* Bw = (MODE == 1) ? g_wpt : g_wqt;

    const int tid  = threadIdx.x;
    const int warp = tid >> 5;
    const int lane = tid & 31;
    const int g    = lane >> 2;
    const int q    = lane & 3;

    const int bm = blockIdx.y * GBM;
    const int bn = blockIdx.x * GBN;
    const int wm = (warp >> 1) * 64;
    const int wn = (warp & 1) * 64;

    const int srow = tid >> 3;
    const int scc  = tid & 7;
    uint32_t soff[8];
#pragma unroll
    for (int p = 0; p < 8; p++) {
        int r = p * 16 + srow;
        soff[p] = (uint32_t)r * GBK + (uint32_t)((scc ^ (r & 7)) * 4);
    }

    float acc[4][8][4];
#pragma unroll
    for (int i = 0; i < 4; i++)
#pragma unroll
        for (int j = 0; j < 8; j++)
#pragma unroll
            for (int e = 0; e < 4; e++) acc[i][j][e] = 0.f;

    const int NIT = K / GBK;

#pragma unroll
    for (int s = 0; s < 2; s++) {
        const uint32_t dA = sbase + (uint32_t)(s * STAGE_W) * 4;
        const uint32_t dB = dA + TILE_W * 4;
        const int k0 = s * GBK;
#pragma unroll
        for (int p = 0; p < 8; p++) {
            const uint32_t* as = Ap + (size_t)(bm + p * 16 + srow) * K + k0 + scc * 4;
            const uint32_t* bs = Bw + (size_t)(bn + p * 16 + srow) * K + k0 + scc * 4;
            CP_ASYNC16(dA + soff[p] * 4, as);
            CP_ASYNC16(dB + soff[p] * 4, bs);
        }
        CP_COMMIT();
    }

    for (int it = 0; it < NIT; it++) {
        CP_WAIT1();
        __syncthreads();

        if (it + 2 < NIT) {
            const int b2 = (it + 2) % NSTAGE;
            const uint32_t dA = sbase + (uint32_t)(b2 * STAGE_W) * 4;
            const uint32_t dB = dA + TILE_W * 4;
            const int k0 = (it + 2) * GBK;
#pragma unroll
            for (int p = 0; p < 8; p++) {
                const uint32_t* as = Ap + (size_t)(bm + p * 16 + srow) * K + k0 + scc * 4;
                const uint32_t* bs = Bw + (size_t)(bn + p * 16 + srow) * K + k0 + scc * 4;
                CP_ASYNC16(dA + soff[p] * 4, as);
                CP_ASYNC16(dB + soff[p] * 4, bs);
            }
        }
        CP_COMMIT();

        const uint32_t* As = sm + (it % NSTAGE) * STAGE_W;
        const uint32_t* Bs = As + TILE_W;
#pragma unroll
        for (int ks = 0; ks < 4; ks++) {
            const int qa0 = ((2 * ks)     ^ g) * 4 + q;
            const int qa1 = ((2 * ks + 1) ^ g) * 4 + q;
            uint32_t a[4][4];
#pragma unroll
            for (int i = 0; i < 4; i++) {
                const int m0 = wm + i * 16 + g;
                a[i][0] = As[m0 * GBK + qa0];
                a[i][1] = As[(m0 + 8) * GBK + qa0];
                a[i][2] = As[m0 * GBK + qa1];
                a[i][3] = As[(m0 + 8) * GBK + qa1];
            }
#pragma unroll
            for (int j = 0; j < 8; j++) {
                const int n0 = wn + j * 8 + g;
                const uint32_t b0 = Bs[n0 * GBK + qa0];
                const uint32_t b1 = Bs[n0 * GBK + qa1];
#pragma unroll
                for (int i = 0; i < 4; i++)
                    mma_tf32(acc[i][j], a[i], b0, b1);
            }
        }
    }

#pragma unroll
    for (int i = 0; i < 4; i++) {
#pragma unroll
        for (int j = 0; j < 8; j++) {
            int r0 = bm + wm + i * 16 + g;
            int n0 = bn + wn + j * 8 + 2 * q;
            if (MODE == 0) {
                int which = n0 >> 11;
                int hh    = (n0 >> 7) & (HEADS - 1);
                int d     = n0 & (HDIM - 1);
                int b     = r0 >> 11;
                uint32_t* base = (which == 0 ? g_q : which == 1 ? g_k : g_v)
                                 + ((size_t)(b * HEADS + hh)) * SEQ * HDIM;
                int s0 = r0 & (SEQ - 1);
                *(uint2*)&base[(size_t)s0 * HDIM + d] =
                    make_uint2(f2tf32(acc[i][j][0]), f2tf32(acc[i][j][1]));
                *(uint2*)&base[(size_t)(s0 + 8) * HDIM + d] =
                    make_uint2(f2tf32(acc[i][j][2]), f2tf32(acc[i][j][3]));
            } else {
                *(float2*)(C + (size_t)r0 * N + n0) =
                    make_float2(acc[i][j][0], acc[i][j][1]);
                *(float2*)(C + (size_t)(r0 + 8) * N + n0) =
                    make_float2(acc[i][j][2], acc[i][j][3]);
            }
        }
    }
}

// =====================================================================
// TF32 tensor-core flash attention (R15 WIN, verbatim: 2-barrier schedule,
// cp.async staging, post-MMA scale, longest blocks first).
// Block = (64 q-rows, head, batch), 128 threads = 4 warps x 16-row tiles.
// =====================================================================
#define AT_BR 64
#define AT_BC 64
#define KST   132
#define PST   68
#define ATTN_SMEM_WORDS (2 * AT_BC * KST + AT_BR * PST)
#define ATTN_SMEM_BYTES (ATTN_SMEM_WORDS * 4)

__global__ void __launch_bounds__(128) attn_tf32_kernel()
{
    extern __shared__ uint32_t smw[];
    const uint32_t sbase = smem_u32(smw);
    uint32_t* Ks = smw;
    uint32_t* Vs = Ks + AT_BC * KST;
    uint32_t* Ps = Vs + AT_BC * KST;
    const uint32_t vbase = sbase + (uint32_t)(AT_BC * KST) * 4;

    const int t    = threadIdx.x;
    const int warp = t >> 5;
    const int lane = t & 31;
    const int g    = lane >> 2;
    const int q    = lane & 3;
    const int wrow = warp * 16;

    const int qt = (gridDim.x - 1) - blockIdx.x;   // longest blocks first
    const int h  = blockIdx.y, b = blockIdx.z;
    const int q0 = qt * AT_BR;
    const size_t headBase = ((size_t)(b * HEADS + h)) * SEQ * HDIM;
    const float scale = 0.08838834764831845f;   // 1/sqrt(128)

    // stage Q tile via cp.async (layout [row][KST])
    {
        const uint32_t* Qg = g_q + headBase + (size_t)q0 * HDIM;
#pragma unroll
        for (int i = 0; i < 16; i++) {
            int idx = t + i * 128;
            int row = idx >> 5, c = idx & 31;
            CP_ASYNC16(sbase + (uint32_t)(row * KST + c * 4) * 4,
                       Qg + (size_t)row * HDIM + c * 4);
        }
        CP_COMMIT();
        CP_WAIT0();
    }
    __syncthreads();

    uint32_t qf[16][4];
#pragma unroll
    for (int ks = 0; ks < 16; ks++) {
        qf[ks][0] = Ks[(wrow + g)     * KST + ks * 8 + q];
        qf[ks][1] = Ks[(wrow + g + 8) * KST + ks * 8 + q];
        qf[ks][2] = Ks[(wrow + g)     * KST + ks * 8 + q + 4];
        qf[ks][3] = Ks[(wrow + g + 8) * KST + ks * 8 + q + 4];
    }

    float accO[16][4];
#pragma unroll
    for (int n = 0; n < 16; n++)
#pragma unroll
        for (int e = 0; e < 4; e++) accO[n][e] = 0.f;

    float m0r = -1e30f, m1r = -1e30f;
    float l0r = 0.f, l1r = 0.f;

    for (int kt = 0; kt <= qt; kt++) {
        __syncthreads();   // previous tile's K/V/P readers done
        {
            const uint32_t* Kg = g_k + headBase + (size_t)(kt * AT_BC) * HDIM;
            const uint32_t* Vg = g_v + headBase + (size_t)(kt * AT_BC) * HDIM;
#pragma unroll
            for (int i = 0; i < 16; i++) {
                int idx = t + i * 128;
                int row = idx >> 5, c = idx & 31;
                const uint32_t off = (uint32_t)(row * KST + c * 4) * 4;
                CP_ASYNC16(sbase + off, Kg + (size_t)row * HDIM + c * 4);
                CP_ASYNC16(vbase + off, Vg + (size_t)row * HDIM + c * 4);
            }
            CP_COMMIT();
            CP_WAIT0();
        }
        __syncthreads();

        float sc[8][4];
#pragma unroll
        for (int n = 0; n < 8; n++)
#pragma unroll
            for (int e = 0; e < 4; e++) sc[n][e] = 0.f;

#pragma unroll
        for (int ks = 0; ks < 16; ks++) {
#pragma unroll
            for (int n = 0; n < 8; n++) {
                uint32_t b0 = Ks[(n * 8 + g) * KST + ks * 8 + q];
                uint32_t b1 = Ks[(n * 8 + g) * KST + ks * 8 + q + 4];
                mma_tf32(sc[n], qf[ks], b0, b1);
            }
        }

        // apply 1/sqrt(D) scale post-MMA
#pragma unroll
        for (int n = 0; n < 8; n++)
#pragma unroll
            for (int e = 0; e < 4; e++) sc[n][e] *= scale;

        if (kt == qt) {
            int r0 = wrow + g, r1 = wrow + g + 8;
#pragma unroll
            for (int n = 0; n < 8; n++) {
                int c0 = n * 8 + 2 * q, c1 = c0 + 1;
                if (c0 > r0) sc[n][0] = -1e30f;
                if (c1 > r0) sc[n][1] = -1e30f;
                if (c0 > r1) sc[n][2] = -1e30f;
                if (c1 > r1) sc[n][3] = -1e30f;
            }
        }

        float pm0 = -1e30f, pm1 = -1e30f;
#pragma unroll
        for (int n = 0; n < 8; n++) {
            pm0 = fmaxf(pm0, fmaxf(sc[n][0], sc[n][1]));
            pm1 = fmaxf(pm1, fmaxf(sc[n][2], sc[n][3]));
        }
        pm0 = fmaxf(pm0, __shfl_xor_sync(0xffffffffu, pm0, 1));
        pm0 = fmaxf(pm0, __shfl_xor_sync(0xffffffffu, pm0, 2));
        pm1 = fmaxf(pm1, __shfl_xor_sync(0xffffffffu, pm1, 1));
        pm1 = fmaxf(pm1, __shfl_xor_sync(0xffffffffu, pm1, 2));

        float mn0 = fmaxf(m0r, pm0);
        float mn1 = fmaxf(m1r, pm1);
        float al0 = __expf(m0r - mn0);
        float al1 = __expf(m1r - mn1);
        m0r = mn0; m1r = mn1;

        float ps0 = 0.f, ps1 = 0.f;
#pragma unroll
        for (int n = 0; n < 8; n++) {
            float p00 = __expf(sc[n][0] - mn0);
            float p01 = __expf(sc[n][1] - mn0);
            float p10 = __expf(sc[n][2] - mn1);
            float p11 = __expf(sc[n][3] - mn1);
            ps0 += p00 + p01;
            ps1 += p10 + p11;
            uint32_t* pr0 = &Ps[(wrow + g) * PST + n * 8 + 2 * q];
            uint32_t* pr1 = &Ps[(wrow + g + 8) * PST + n * 8 + 2 * q];
            pr0[0] = f2tf32(p00); pr0[1] = f2tf32(p01);
            pr1[0] = f2tf32(p10); pr1[1] = f2tf32(p11);
        }
        ps0 += __shfl_xor_sync(0xffffffffu, ps0, 1);
        ps0 += __shfl_xor_sync(0xffffffffu, ps0, 2);
        ps1 += __shfl_xor_sync(0xffffffffu, ps1, 1);
        ps1 += __shfl_xor_sync(0xffffffffu, ps1, 2);
        l0r = l0r * al0 + ps0;
        l1r = l1r * al1 + ps1;

#pragma unroll
        for (int n = 0; n < 16; n++) {
            accO[n][0] *= al0; accO[n][1] *= al0;
            accO[n][2] *= al1; accO[n][3] *= al1;
        }

        __syncwarp();

#pragma unroll
        for (int ks = 0; ks < 8; ks++) {
            uint32_t pa[4];
            pa[0] = Ps[(wrow + g)     * PST + ks * 8 + q];
            pa[1] = Ps[(wrow + g + 8) * PST + ks * 8 + q];
            pa[2] = Ps[(wrow + g)     * PST + ks * 8 + q + 4];
            pa[3] = Ps[(wrow + g + 8) * PST + ks * 8 + q + 4];
#pragma unroll
            for (int n = 0; n < 16; n++) {
                uint32_t b0 = Vs[(ks * 8 + q)     * KST + n * 8 + g];
                uint32_t b1 = Vs[(ks * 8 + q + 4) * KST + n * 8 + g];
                mma_tf32(accO[n], pa, b0, b1);
            }
        }
        __syncwarp();
    }

    // epilogue: normalize, write tf32 bits to g_att
    float inv0 = 1.0f / l0r;
    float inv1 = 1.0f / l1r;
    size_t row0 = (size_t)(b * SEQ + q0 + wrow + g);
    size_t row1 = row0 + 8;
#pragma unroll
    for (int n = 0; n < 16; n++) {
        int d = n * 8 + 2 * q;
        *(uint2*)&g_att[row0 * EMB + h * HDIM + d] =
            make_uint2(f2tf32(accO[n][0] * inv0), f2tf32(accO[n][1] * inv0));
        *(uint2*)&g_att[row1 * EMB + h * HDIM + d] =
            make_uint2(f2tf32(accO[n][2] * inv1), f2tf32(accO[n][3] * inv1));
    }
}

// =====================================================================
// launch
// =====================================================================
extern "C" void kernel_launch(void* const* d_in, const int* in_sizes, int n_in,
                              void* d_out, int out_size)
{
    (void)in_sizes; (void)n_in; (void)out_size;
    const float* x     = (const float*)d_in[0];   // [B,S,E]
    const float* Wqkv  = (const float*)d_in[1];   // [3E,E]
    const float* Wproj = (const float*)d_in[2];   // [E,E]
    float* out = (float*)d_out;                   // [B,S,E]

    cudaFuncSetAttribute(sgemm_tf32_v6<0>,
                         cudaFuncAttributeMaxDynamicSharedMemorySize,
                         GEMM_SMEM_BYTES);
    cudaFuncSetAttribute(sgemm_tf32_v6<1>,
                         cudaFuncAttributeMaxDynamicSharedMemorySize,
                         GEMM_SMEM_BYTES);
    cudaFuncSetAttribute(attn_tf32_kernel,
                         cudaFuncAttributeMaxDynamicSharedMemorySize,
                         ATTN_SMEM_BYTES);

    // 0) fused prepass: fp32 -> tf32 bit buffers (one launch)
    cvt_all_kernel<<<2048, 256>>>(x, Wqkv, Wproj);

    // 1) qkv = x @ Wqkv^T -> g_q/g_k/g_v (tf32 bits, [B,H,S,D])
    dim3 g1(EMB3 / GBN, MROWS / GBM);
    sgemm_tf32_v6<0><<<g1, 128, GEMM_SMEM_BYTES>>>(nullptr, MROWS, EMB3, EMB);

    // 2) causal flash attention -> g_att (tf32 bits, [B,S,E])
    dim3 g2(SEQ / AT_BR, HEADS, BATCH);
    attn_tf32_kernel<<<g2, 128, ATTN_SMEM_BYTES>>>();

    // 3) out = g_att @ Wproj^T (fp32 out)
    dim3 g3(EMB / GBN, MROWS / GBM);
    sgemm_tf32_v6<1><<<g3, 128, GEMM_SMEM_BYTES>>>(out, MROWS, EMB, EMB);
}